// round 4
// baseline (speedup 1.0000x reference)
#include <cuda_runtime.h>

#define HH 128
#define WW 256
#define HWP 32768
#define CC 64
#define BB 2
#define KK 16

typedef unsigned long long u64;

// ---------------- scratch ----------------------------------------------------
__device__ float g_tmp[4 * CC * HWP];
__device__ float g_buf[4 * CC * HWP];
__device__ float g_Q[BB * HWP * CC];
__device__ float g_S[BB * HWP * CC];
__device__ float g_R[BB * HWP * CC];
__device__ float g_battn[BB * HWP * CC];
__device__ u64 g_wc[2][2][576 * 16];  // conv pair-packed
__device__ u64 g_wq[3][4096];         // qsr dup-packed
__device__ u64 g_wfu[8192];           // fuse dup-packed [cin*64+co]

// ---------------- packed f32x2 helpers ---------------------------------------
__device__ __forceinline__ u64 pk2(float lo, float hi) {
    u64 r;
    asm("mov.b64 %0, {%1, %2};" : "=l"(r) : "f"(lo), "f"(hi));
    return r;
}
__device__ __forceinline__ void upk2(u64 v, float& lo, float& hi) {
    asm("mov.b64 {%0, %1}, %2;" : "=f"(lo), "=f"(hi) : "l"(v));
}
__device__ __forceinline__ u64 fma2(u64 a, u64 b, u64 c) {
    u64 d;
    asm("fma.rn.f32x2 %0, %1, %2, %3;" : "=l"(d) : "l"(a), "l"(b), "l"(c));
    return d;
}

// ---------------- prep: pack weights ------------------------------------------
__global__ void __launch_bounds__(256) prep_k(const float* __restrict__ w1,
                                              const float* __restrict__ w2,
                                              const float* __restrict__ qw,
                                              const float* __restrict__ sw,
                                              const float* __restrict__ rw,
                                              const float* __restrict__ fw) {
    int i = blockIdx.x * 256 + threadIdx.x;  // 0..57343
    if (i < 36864) {
        int conv = i / 18432;
        int r = i % 18432;
        int h = r / 9216;
        int j = r % 9216;
        int cpl = j & 15;
        int ct = j >> 4;
        int cin = ct / 9, tap = ct - cin * 9;
        int co = h * 32 + 2 * cpl;
        const float* w = conv ? w2 : w1;
        g_wc[conv][h][j] = pk2(w[(co * 64 + cin) * 9 + tap], w[((co + 1) * 64 + cin) * 9 + tap]);
    } else if (i < 49152) {
        int j = i - 36864;
        int mat = j >> 12;
        int e = j & 4095;
        int cin = e >> 6, co = e & 63;
        const float* w = (mat == 0) ? qw : (mat == 1) ? sw : rw;
        float v = w[co * 64 + cin];
        g_wq[mat][e] = pk2(v, v);
    } else {
        int j = i - 49152;  // 0..8191
        int cin = j >> 6, co = j & 63;
        float v = fw[co * 128 + cin];
        g_wfu[j] = pk2(v, v);
    }
}

// ---------------- conv 3x3 (pad=1), 64->64, dup-packed tile -------------------
// Block 256 thr, 2/SM. Tile: 32x x 8y x 32 couts (cohalf).
#define CONV_SMEM (73728 + 21760)

template <int MODE>
__global__ void __launch_bounds__(256, 2) conv3x3_k(const float* __restrict__ xl,
                                                    const float* __restrict__ xr) {
    extern __shared__ unsigned char dynsm[];
    u64* wsm = (u64*)dynsm;                  // 9216 pair-packed
    u64* tile = (u64*)(dynsm + 73728);       // 2720 dup-packed: [c*340 + r*34 + x]

    const int t = threadIdx.x;
    const int img = blockIdx.z >> 1;
    const int h = blockIdx.z & 1;
    const int gx0 = blockIdx.x * 32;
    const int gy0 = blockIdx.y * 8;

    const float* in;
    if (MODE == 0)
        in = (img < 2) ? (xl + img * CC * HWP) : (xr + (img - 2) * CC * HWP);
    else
        in = g_tmp + img * CC * HWP;

    {
        const u64* ws = g_wc[MODE][h];
        for (int j = t; j < 9216; j += 256) wsm[j] = ws[j];
    }

    const int cg = t >> 6;
    const int pg = t & 63;
    const int ox = pg & 31;
    const int ry = (pg >> 5) * 4;

    u64 acc[4][4];
#pragma unroll
    for (int rr = 0; rr < 4; rr++)
#pragma unroll
        for (int cp = 0; cp < 4; cp++) acc[rr][cp] = 0ull;

    for (int cc0 = 0; cc0 < 64; cc0 += 8) {
        __syncthreads();
        for (int i = t; i < 2720; i += 256) {
            int c = i / 340;
            int rem = i - c * 340;
            int r = rem / 34;
            int x = rem - r * 34;
            int gy = gy0 - 1 + r, gx = gx0 - 1 + x;
            float v = 0.f;
            if ((unsigned)gy < HH && (unsigned)gx < WW)
                v = in[(cc0 + c) * HWP + gy * WW + gx];
            tile[i] = pk2(v, v);
        }
        __syncthreads();

#pragma unroll 2
        for (int c = 0; c < 8; c++) {
            const u64* tb = tile + c * 340 + ry * 34 + ox;
            u64 dv[6][3];
#pragma unroll
            for (int r = 0; r < 6; r++)
#pragma unroll
                for (int dx = 0; dx < 3; dx++) dv[r][dx] = tb[r * 34 + dx];
            const u64* wb = wsm + (cc0 + c) * 144 + cg * 4;
#pragma unroll
            for (int dy = 0; dy < 3; dy++)
#pragma unroll
                for (int dx = 0; dx < 3; dx++) {
                    const u64* wt = wb + (dy * 3 + dx) * 16;
#pragma unroll
                    for (int cp = 0; cp < 4; cp++) {
                        u64 w2 = wt[cp];
#pragma unroll
                        for (int rr = 0; rr < 4; rr++)
                            acc[rr][cp] = fma2(w2, dv[rr + dy][dx], acc[rr][cp]);
                    }
                }
        }
    }

    float* out = ((MODE == 0) ? g_tmp : g_buf) + img * CC * HWP;
    const float* res = nullptr;
    if (MODE == 1)
        res = (img < 2) ? (xl + img * CC * HWP) : (xr + (img - 2) * CC * HWP);

#pragma unroll
    for (int rr = 0; rr < 4; rr++) {
        const int gy = gy0 + ry + rr;
#pragma unroll
        for (int cp = 0; cp < 4; cp++) {
            float lo, hi;
            upk2(acc[rr][cp], lo, hi);
            int co = h * 32 + cg * 8 + 2 * cp;
            int off0 = co * HWP + gy * WW + gx0 + ox;
            int off1 = off0 + HWP;
            if (MODE == 0) {
                lo = lo > 0.f ? lo : 0.1f * lo;
                hi = hi > 0.f ? hi : 0.1f * hi;
            } else {
                lo += res[off0];
                hi += res[off1];
            }
            out[off0] = lo;
            out[off1] = hi;
        }
    }
}

// ---------------- Q/S/R 1x1: smem-staged GEMM ---------------------------------
// Block 256 thr, 256 px, 64 couts, one mat. 2 blocks/SM.
#define QSR_SMEM (32768 + 17408)

__global__ void __launch_bounds__(256, 2) qsr_k(const float* __restrict__ b1b,
                                                const float* __restrict__ b2b,
                                                const float* __restrict__ b3b) {
    extern __shared__ unsigned char dynsm[];
    u64* wsm = (u64*)dynsm;                    // 4096 dup-packed
    float* tile = (float*)(dynsm + 32768);     // 16 cin x 256 px
    float* st = (float*)(dynsm + 32768);       // reused: 64 px x 65

    const int t = threadIdx.x;
    const int mat = blockIdx.y;
    const int p0 = blockIdx.x * 256;
    const int b = p0 >> 15;
    const int lp = p0 & 32767;

    const float* in = g_buf + (((mat == 0) ? 0 : 2) + b) * CC * HWP + lp;
    float* outp = ((mat == 0) ? g_Q : (mat == 1) ? g_S : g_R) + p0 * 64;
    const float* bias = (mat == 0) ? b1b : (mat == 1) ? b2b : b3b;

    {
        const u64* ws = g_wq[mat];
        for (int j = t; j < 4096; j += 256) wsm[j] = ws[j];
    }

    const int cg = t >> 5;
    const int tx = t & 31;

    u64 acc[8][4];
#pragma unroll
    for (int co = 0; co < 8; co++)
#pragma unroll
        for (int j = 0; j < 4; j++) acc[co][j] = 0ull;

    for (int cc0 = 0; cc0 < 64; cc0 += 16) {
        __syncthreads();
#pragma unroll
        for (int k = 0; k < 16; k++) {
            int j = t + k * 256;
            int cin = j >> 8, px = j & 255;
            tile[j] = in[(cc0 + cin) * HWP + px];
        }
        __syncthreads();
#pragma unroll 4
        for (int ci = 0; ci < 16; ci++) {
            u64 v[4];
#pragma unroll
            for (int j = 0; j < 4; j++)
                v[j] = *(const u64*)&tile[ci * 256 + 2 * tx + 64 * j];
            const u64* wb = wsm + (cc0 + ci) * 64 + cg * 8;
#pragma unroll
            for (int co = 0; co < 8; co++) {
                u64 w2 = wb[co];
#pragma unroll
                for (int j = 0; j < 4; j++) acc[co][j] = fma2(w2, v[j], acc[co][j]);
            }
        }
    }

#pragma unroll
    for (int j = 0; j < 4; j++) {
        __syncthreads();
#pragma unroll
        for (int co = 0; co < 8; co++) {
            float lo, hi;
            upk2(acc[co][j], lo, hi);
            st[(2 * tx) * 65 + cg * 8 + co] = lo;
            st[(2 * tx + 1) * 65 + cg * 8 + co] = hi;
        }
        __syncthreads();
        for (int i = t; i < 4096; i += 256) {
            int px = i >> 6, c = i & 63;
            outp[(64 * j + px) * 64 + c] = st[px * 65 + c] + bias[c];
        }
    }
}

// ---------------- attention: warp per pixel ----------------------------------
__global__ void __launch_bounds__(256) attn_k(const int* __restrict__ xxs,
                                              const int* __restrict__ yys,
                                              float* __restrict__ Mout) {
    const int t = threadIdx.x;
    const int lane = t & 31;
    const int p = blockIdx.x * 8 + (t >> 5);
    const int b = p >> 15;

    int fl = 0;
    if (lane < 16) fl = xxs[p * 16 + lane] * WW + yys[p * 16 + lane];

    const float q0 = g_Q[p * 64 + lane];
    const float q1 = g_Q[p * 64 + lane + 32];
    const float* Sb = g_S + b * HWP * 64;
    const float* Rb = g_R + b * HWP * 64;

    float sc[16];
    int bs[16];
#pragma unroll
    for (int k = 0; k < 16; k++) {
        int fk = __shfl_sync(0xffffffffu, fl, k);
        int base = fk * 64;
        bs[k] = base;
        float part = q0 * Sb[base + lane] + q1 * Sb[base + lane + 32];
#pragma unroll
        for (int o = 16; o; o >>= 1) part += __shfl_xor_sync(0xffffffffu, part, o);
        sc[k] = part;
    }

    float mx = sc[0];
#pragma unroll
    for (int k = 1; k < 16; k++) mx = fmaxf(mx, sc[k]);
    float sum = 0.f;
#pragma unroll
    for (int k = 0; k < 16; k++) { sc[k] = __expf(sc[k] - mx); sum += sc[k]; }
    const float inv = 1.f / sum;

    float acc0 = 0.f, acc1 = 0.f, mv = 0.f;
#pragma unroll
    for (int k = 0; k < 16; k++) {
        float m = sc[k] * inv;
        acc0 += m * Rb[bs[k] + lane];
        acc1 += m * Rb[bs[k] + lane + 32];
        if (lane == k) mv = m;
    }

    g_battn[p * 64 + lane] = acc0;
    g_battn[p * 64 + lane + 32] = acc1;
    if (lane < 16) Mout[p * 16 + lane] = mv;
}

// ---------------- fusion 1x1: concat(buf_attn, x_left) -> out -----------------
#define FUSE_SMEM (65536 + 8448)

__global__ void __launch_bounds__(256) fuse_k(const float* __restrict__ xl,
                                              const float* __restrict__ fb,
                                              float* __restrict__ out) {
    extern __shared__ unsigned char dynsm[];
    u64* wsm = (u64*)dynsm;                    // 8192 dup-packed
    float* vsm = (float*)(dynsm + 65536);      // 8 x 258

    const int t = threadIdx.x;
    const int b = blockIdx.y;
    const int p0 = blockIdx.x * 256;

    for (int j = t; j < 8192; j += 256) wsm[j] = g_wfu[j];

    const float* ba = g_battn + b * HWP * 64;
    const float* xlb = xl + b * 64 * HWP;
    const int cg = t >> 6, q = t & 63;
    u64 acc[16][2];
#pragma unroll
    for (int c = 0; c < 16; c++) { acc[c][0] = 0ull; acc[c][1] = 0ull; }
    __syncthreads();

    for (int cc0 = 0; cc0 < 64; cc0 += 8) {
        __syncthreads();
        for (int i = t; i < 2048; i += 256) {
            int c = i & 7, px = i >> 3;
            vsm[c * 258 + px] = ba[(p0 + px) * 64 + cc0 + c];
        }
        __syncthreads();
#pragma unroll
        for (int cl = 0; cl < 8; cl++) {
            const int cin = cc0 + cl;
            u64 v0 = *(const u64*)&vsm[cl * 258 + 2 * q];
            u64 v1 = *(const u64*)&vsm[cl * 258 + 128 + 2 * q];
            const u64* wb = wsm + cin * 64 + cg * 16;
#pragma unroll
            for (int c = 0; c < 16; c++) {
                u64 w2 = wb[c];
                acc[c][0] = fma2(w2, v0, acc[c][0]);
                acc[c][1] = fma2(w2, v1, acc[c][1]);
            }
        }
    }
#pragma unroll 4
    for (int cin = 64; cin < 128; cin++) {
        u64 v0 = *(const u64*)(xlb + (cin - 64) * HWP + p0 + 2 * q);
        u64 v1 = *(const u64*)(xlb + (cin - 64) * HWP + p0 + 128 + 2 * q);
        const u64* wb = wsm + cin * 64 + cg * 16;
#pragma unroll
        for (int c = 0; c < 16; c++) {
            u64 w2 = wb[c];
            acc[c][0] = fma2(w2, v0, acc[c][0]);
            acc[c][1] = fma2(w2, v1, acc[c][1]);
        }
    }

#pragma unroll
    for (int c = 0; c < 16; c++) {
        const int co = cg * 16 + c;
        const float bb = fb[co];
#pragma unroll
        for (int r = 0; r < 2; r++) {
            float lo, hi;
            upk2(acc[c][r], lo, hi);
            float2 o;
            o.x = lo + bb;
            o.y = hi + bb;
            *(float2*)(out + (b * 64 + co) * HWP + p0 + 128 * r + 2 * q) = o;
        }
    }
}

// ---------------- launch ------------------------------------------------------
extern "C" void kernel_launch(void* const* d_in, const int* in_sizes, int n_in,
                              void* d_out, int out_size) {
    const float* xl = (const float*)d_in[0];
    const float* xr = (const float*)d_in[1];
    const int* xxs = (const int*)d_in[2];
    const int* yys = (const int*)d_in[3];
    const int wbase = (in_sizes[4] == 1) ? 5 : 4;
    const float* rb_w1 = (const float*)d_in[wbase + 0];
    const float* rb_w2 = (const float*)d_in[wbase + 1];
    const float* b1w = (const float*)d_in[wbase + 2];
    const float* b1b = (const float*)d_in[wbase + 3];
    const float* b2w = (const float*)d_in[wbase + 4];
    const float* b2b = (const float*)d_in[wbase + 5];
    const float* b3w = (const float*)d_in[wbase + 6];
    const float* b3b = (const float*)d_in[wbase + 7];
    const float* fw = (const float*)d_in[wbase + 8];
    const float* fb = (const float*)d_in[wbase + 9];

    float* out = (float*)d_out;
    float* Mout = out + BB * CC * HWP;

    cudaFuncSetAttribute(conv3x3_k<0>, cudaFuncAttributeMaxDynamicSharedMemorySize, CONV_SMEM);
    cudaFuncSetAttribute(conv3x3_k<1>, cudaFuncAttributeMaxDynamicSharedMemorySize, CONV_SMEM);
    cudaFuncSetAttribute(qsr_k, cudaFuncAttributeMaxDynamicSharedMemorySize, QSR_SMEM);
    cudaFuncSetAttribute(fuse_k, cudaFuncAttributeMaxDynamicSharedMemorySize, FUSE_SMEM);

    prep_k<<<224, 256>>>(rb_w1, rb_w2, b1w, b2w, b3w, fw);

    dim3 g3(WW / 32, HH / 8, 8);
    conv3x3_k<0><<<g3, 256, CONV_SMEM>>>(xl, xr);
    conv3x3_k<1><<<g3, 256, CONV_SMEM>>>(xl, xr);

    qsr_k<<<dim3(BB * HWP / 256, 3), 256, QSR_SMEM>>>(b1b, b2b, b3b);

    attn_k<<<BB * HWP / 8, 256>>>(xxs, yys, Mout);

    fuse_k<<<dim3(HWP / 256, BB), 256, FUSE_SMEM>>>(xl, fb, out);
}

// round 7
// speedup vs baseline: 1.4571x; 1.4571x over previous
#include <cuda_runtime.h>
#include <cuda_fp16.h>
#include <cstdint>

#define HH 128
#define WW 256
#define HWP 32768
#define CC 64
#define BB 2
#define KK 16
#define CHW (CC * HWP)

typedef unsigned long long u64;
typedef unsigned int u32;

// ---------------- scratch ----------------------------------------------------
__device__ u32 g_xs[4 * HWP * CC];     // packed {hi16,lo16} fp16 split of x, pixel-major
__device__ u32 g_ts[4 * HWP * CC];     // packed split of conv1 output, pixel-major
__device__ float g_buf[4 * CHW];       // conv2 output (fp32, channel-major)
__device__ float g_Q[BB * HWP * CC];
__device__ float g_S[BB * HWP * CC];
__device__ float g_R[BB * HWP * CC];
__device__ float g_battn[BB * HWP * CC];
__device__ u64 g_wf[2 * 9 * 2 * 4 * 8 * 32];  // conv B-fragments, lane-ordered (36864)
__device__ u64 g_wq[3][4096];                 // qsr dup-packed
__device__ u64 g_wfu[8192];                   // fuse dup-packed

// ---------------- f32x2 helpers ----------------------------------------------
__device__ __forceinline__ u64 pk2(float lo, float hi) {
    u64 r;
    asm("mov.b64 %0, {%1, %2};" : "=l"(r) : "f"(lo), "f"(hi));
    return r;
}
__device__ __forceinline__ void upk2(u64 v, float& lo, float& hi) {
    asm("mov.b64 {%0, %1}, %2;" : "=f"(lo), "=f"(hi) : "l"(v));
}
__device__ __forceinline__ u64 fma2(u64 a, u64 b, u64 c) {
    u64 d;
    asm("fma.rn.f32x2 %0, %1, %2, %3;" : "=l"(d) : "l"(a), "l"(b), "l"(c));
    return d;
}

// ---------------- fp16 split helpers ------------------------------------------
__device__ __forceinline__ u32 splitpack(float v) {
    __half h = __float2half_rn(v);
    __half l = __float2half_rn(v - __half2float(h));
    return (u32)__half_as_ushort(h) | ((u32)__half_as_ushort(l) << 16);
}

// ---------------- mma.sync m16n8k16 -------------------------------------------
__device__ __forceinline__ void mma16816(float c[4], const u32 a[4], u64 b) {
    u32 b0 = (u32)b, b1 = (u32)(b >> 32);
    asm volatile(
        "mma.sync.aligned.m16n8k16.row.col.f32.f16.f16.f32 "
        "{%0,%1,%2,%3},{%4,%5,%6,%7},{%8,%9},{%0,%1,%2,%3};"
        : "+f"(c[0]), "+f"(c[1]), "+f"(c[2]), "+f"(c[3])
        : "r"(a[0]), "r"(a[1]), "r"(a[2]), "r"(a[3]), "r"(b0), "r"(b1));
}

// ---------------- prep: weights ------------------------------------------------
// conv fragments: i in [0,36864): [conv][tap][split][k][n][lane]
__global__ void __launch_bounds__(256) prep_w(const float* __restrict__ w1,
                                              const float* __restrict__ w2,
                                              const float* __restrict__ qw,
                                              const float* __restrict__ sw,
                                              const float* __restrict__ rw,
                                              const float* __restrict__ fw) {
    int i = blockIdx.x * 256 + threadIdx.x;  // 0..57343
    if (i < 36864) {
        int conv = i / 18432;
        int r = i % 18432;
        int tap = r / 2048;
        int r2 = r % 2048;
        int split = (r2 >> 10) & 1;
        int k = (r2 >> 8) & 3;
        int n = (r2 >> 5) & 7;
        int lane = r2 & 31;
        int g = lane >> 2, tig = lane & 3;
        int cin0 = k * 16 + 2 * tig;
        int co = n * 8 + g;
        const float* w = conv ? w2 : w1;
        unsigned short hv[4];
#pragma unroll
        for (int e = 0; e < 4; e++) {
            int cin = cin0 + (e & 1) + (e >> 1) * 8;
            float v = w[(co * 64 + cin) * 9 + tap];
            __half h = __float2half_rn(v);
            __half o = split ? __float2half_rn(v - __half2float(h)) : h;
            hv[e] = __half_as_ushort(o);
        }
        u32 b0 = (u32)hv[0] | ((u32)hv[1] << 16);
        u32 b1 = (u32)hv[2] | ((u32)hv[3] << 16);
        g_wf[i] = (u64)b0 | ((u64)b1 << 32);
    } else if (i < 49152) {
        int j = i - 36864;
        int mat = j >> 12;
        int e = j & 4095;
        int cin = e >> 6, co = e & 63;
        const float* w = (mat == 0) ? qw : (mat == 1) ? sw : rw;
        float v = w[co * 64 + cin];
        g_wq[mat][e] = pk2(v, v);
    } else {
        int j = i - 49152;
        int cin = j >> 6, co = j & 63;
        float v = fw[co * 128 + cin];
        g_wfu[j] = pk2(v, v);
    }
}

// ---------------- prep: split x into pixel-major packed u32 -------------------
__global__ void __launch_bounds__(256) prep_x(const float* __restrict__ xl,
                                              const float* __restrict__ xr) {
    __shared__ float tile[64 * 65];
    const int t = threadIdx.x;
    const int img = blockIdx.x >> 9;
    const int px0 = (blockIdx.x & 511) * 64;
    const float* in = (img < 2) ? (xl + img * CHW) : (xr + (img - 2) * CHW);

    for (int i = t; i < 4096; i += 256) {
        int cin = i >> 6, px = i & 63;
        tile[px * 65 + cin] = in[cin * HWP + px0 + px];
    }
    __syncthreads();
    for (int i = t; i < 4096; i += 256) {
        int px = i >> 6, cin = i & 63;
        g_xs[(img * HWP + px0 + px) * 64 + cin] = splitpack(tile[px * 65 + cin]);
    }
}

// ---------------- conv3x3 via mma.sync (fp16 split, register frags) -----------
// CTA = 128-px strip x 64 couts, 8 warps; warp = 16 px x 64 co (8 n-tiles).
// MODE 0: in g_xs, out g_ts (leaky + resplit, pixel-major packed)
// MODE 1: in g_ts, out g_buf (fp32 channel-major, + residual)
template <int MODE>
__global__ void __launch_bounds__(256) conv_mma(const float* __restrict__ xl,
                                                const float* __restrict__ xr) {
    const int t = threadIdx.x;
    const int w = t >> 5;
    const int lane = t & 31;
    const int g = lane >> 2, tig = lane & 3;

    const int s = blockIdx.x;
    const int img = s >> 8;
    const int r = s & 255;
    const int y = r >> 1;
    const int x0 = (r & 1) * 128;

    const u32* inp = ((MODE == 0) ? g_xs : g_ts) + img * HWP * 64;
    const int xa = x0 + w * 16 + g;  // x position of row g (pre-shift)

    float acc[8][4];
#pragma unroll
    for (int n = 0; n < 8; n++)
#pragma unroll
        for (int c = 0; c < 4; c++) acc[n][c] = 0.f;

#pragma unroll
    for (int tap = 0; tap < 9; tap++) {
        const int dy = tap / 3, dx = tap - dy * 3;
        const int yy = y + dy - 1;
        if ((unsigned)yy >= HH) continue;
        const int gxa = xa + dx - 1;
        const bool va = (unsigned)gxa < WW;
        const bool vb = (unsigned)(gxa + 8) < WW;
        const u32* pa = inp + (yy * WW + gxa) * 64 + 2 * tig;
        const u32* pb = pa + 8 * 64;
        const u64* WB = g_wf + (MODE * 9 + tap) * 2048 + lane;

#pragma unroll
        for (int k = 0; k < 4; k++) {
            u64 LA0 = 0, LA1 = 0, LB0 = 0, LB1 = 0;
            if (va) {
                LA0 = *(const u64*)(pa + k * 16);
                LA1 = *(const u64*)(pa + k * 16 + 8);
            }
            if (vb) {
                LB0 = *(const u64*)(pb + k * 16);
                LB1 = *(const u64*)(pb + k * 16 + 8);
            }
            u32 ah[4], al[4];
            {
                u32 x00 = (u32)LA0, x01 = (u32)(LA0 >> 32);
                u32 x10 = (u32)LB0, x11 = (u32)(LB0 >> 32);
                u32 x20 = (u32)LA1, x21 = (u32)(LA1 >> 32);
                u32 x30 = (u32)LB1, x31 = (u32)(LB1 >> 32);
                ah[0] = __byte_perm(x00, x01, 0x5410);
                al[0] = __byte_perm(x00, x01, 0x7632);
                ah[1] = __byte_perm(x10, x11, 0x5410);
                al[1] = __byte_perm(x10, x11, 0x7632);
                ah[2] = __byte_perm(x20, x21, 0x5410);
                al[2] = __byte_perm(x20, x21, 0x7632);
                ah[3] = __byte_perm(x30, x31, 0x5410);
                al[3] = __byte_perm(x30, x31, 0x7632);
            }
            const u64* WH = WB + k * 256;
            const u64* WL = WH + 1024;
#pragma unroll
            for (int n = 0; n < 8; n++) {
                u64 bh = WH[n * 32];
                u64 bl = WL[n * 32];
                mma16816(acc[n], ah, bh);
                mma16816(acc[n], ah, bl);
                mma16816(acc[n], al, bh);
            }
        }
    }

    const int bp = y * WW + x0 + w * 16 + g;  // pixel of row g; +8 for row g+8
    if (MODE == 0) {
        u32* o0 = g_ts + (img * HWP + bp) * 64;
        u32* o1 = o0 + 8 * 64;
#pragma unroll
        for (int n = 0; n < 8; n++) {
            const int co0 = n * 8 + 2 * tig;
            float v0 = acc[n][0], v1 = acc[n][1], v2 = acc[n][2], v3 = acc[n][3];
            v0 = v0 > 0.f ? v0 : 0.1f * v0;
            v1 = v1 > 0.f ? v1 : 0.1f * v1;
            v2 = v2 > 0.f ? v2 : 0.1f * v2;
            v3 = v3 > 0.f ? v3 : 0.1f * v3;
            u32 p0 = splitpack(v0), p1 = splitpack(v1);
            u32 p2 = splitpack(v2), p3 = splitpack(v3);
            *(u64*)(o0 + co0) = (u64)p0 | ((u64)p1 << 32);
            *(u64*)(o1 + co0) = (u64)p2 | ((u64)p3 << 32);
        }
    } else {
        const float* res = (img < 2) ? (xl + img * CHW) : (xr + (img - 2) * CHW);
        float* ob = g_buf + img * CHW;
#pragma unroll
        for (int n = 0; n < 8; n++) {
            const int co0 = n * 8 + 2 * tig;
            ob[co0 * HWP + bp] = acc[n][0] + res[co0 * HWP + bp];
            ob[(co0 + 1) * HWP + bp] = acc[n][1] + res[(co0 + 1) * HWP + bp];
            ob[co0 * HWP + bp + 8] = acc[n][2] + res[co0 * HWP + bp + 8];
            ob[(co0 + 1) * HWP + bp + 8] = acc[n][3] + res[(co0 + 1) * HWP + bp + 8];
        }
    }
}

// ---------------- Q/S/R 1x1: smem-staged GEMM (R4) ----------------------------
#define QSR_SMEM (32768 + 17408)
__global__ void __launch_bounds__(256, 2) qsr_k(const float* __restrict__ b1b,
                                                const float* __restrict__ b2b,
                                                const float* __restrict__ b3b) {
    extern __shared__ unsigned char dynsm[];
    u64* wsm = (u64*)dynsm;
    float* tile = (float*)(dynsm + 32768);
    float* st = (float*)(dynsm + 32768);

    const int t = threadIdx.x;
    const int mat = blockIdx.y;
    const int p0 = blockIdx.x * 256;
    const int b = p0 >> 15;
    const int lp = p0 & 32767;

    const float* in = g_buf + (((mat == 0) ? 0 : 2) + b) * CHW + lp;
    float* outp = ((mat == 0) ? g_Q : (mat == 1) ? g_S : g_R) + p0 * 64;
    const float* bias = (mat == 0) ? b1b : (mat == 1) ? b2b : b3b;

    {
        const u64* ws = g_wq[mat];
        for (int j = t; j < 4096; j += 256) wsm[j] = ws[j];
    }

    const int cg = t >> 5;
    const int tx = t & 31;

    u64 acc[8][4];
#pragma unroll
    for (int co = 0; co < 8; co++)
#pragma unroll
        for (int j = 0; j < 4; j++) acc[co][j] = 0ull;

    for (int cc0 = 0; cc0 < 64; cc0 += 16) {
        __syncthreads();
#pragma unroll
        for (int k = 0; k < 16; k++) {
            int j = t + k * 256;
            int cin = j >> 8, px = j & 255;
            tile[j] = in[(cc0 + cin) * HWP + px];
        }
        __syncthreads();
#pragma unroll 4
        for (int ci = 0; ci < 16; ci++) {
            u64 v[4];
#pragma unroll
            for (int j = 0; j < 4; j++) v[j] = *(const u64*)&tile[ci * 256 + 2 * tx + 64 * j];
            const u64* wb = wsm + (cc0 + ci) * 64 + cg * 8;
#pragma unroll
            for (int co = 0; co < 8; co++) {
                u64 w2 = wb[co];
#pragma unroll
                for (int j = 0; j < 4; j++) acc[co][j] = fma2(w2, v[j], acc[co][j]);
            }
        }
    }

#pragma unroll
    for (int j = 0; j < 4; j++) {
        __syncthreads();
#pragma unroll
        for (int co = 0; co < 8; co++) {
            float lo, hi;
            upk2(acc[co][j], lo, hi);
            st[(2 * tx) * 65 + cg * 8 + co] = lo;
            st[(2 * tx + 1) * 65 + cg * 8 + co] = hi;
        }
        __syncthreads();
        for (int i = t; i < 4096; i += 256) {
            int px = i >> 6, c = i & 63;
            outp[(64 * j + px) * 64 + c] = st[px * 65 + c] + bias[c];
        }
    }
}

// ---------------- attention: warp per pixel ----------------------------------
__global__ void __launch_bounds__(256) attn_k(const int* __restrict__ xxs,
                                              const int* __restrict__ yys,
                                              float* __restrict__ Mout) {
    const int t = threadIdx.x;
    const int lane = t & 31;
    const int p = blockIdx.x * 8 + (t >> 5);
    const int b = p >> 15;

    int fl = 0;
    if (lane < 16) fl = xxs[p * 16 + lane] * WW + yys[p * 16 + lane];

    const float q0 = g_Q[p * 64 + lane];
    const float q1 = g_Q[p * 64 + lane + 32];
    const float* Sb = g_S + b * HWP * 64;
    const float* Rb = g_R + b * HWP * 64;

    float sc[16];
    int bs[16];
#pragma unroll
    for (int k = 0; k < 16; k++) {
        int fk = __shfl_sync(0xffffffffu, fl, k);
        int base = fk * 64;
        bs[k] = base;
        float part = q0 * Sb[base + lane] + q1 * Sb[base + lane + 32];
#pragma unroll
        for (int o = 16; o; o >>= 1) part += __shfl_xor_sync(0xffffffffu, part, o);
        sc[k] = part;
    }

    float mx = sc[0];
#pragma unroll
    for (int k = 1; k < 16; k++) mx = fmaxf(mx, sc[k]);
    float sum = 0.f;
#pragma unroll
    for (int k = 0; k < 16; k++) {
        sc[k] = __expf(sc[k] - mx);
        sum += sc[k];
    }
    const float inv = 1.f / sum;

    float acc0 = 0.f, acc1 = 0.f, mv = 0.f;
#pragma unroll
    for (int k = 0; k < 16; k++) {
        float m = sc[k] * inv;
        acc0 += m * Rb[bs[k] + lane];
        acc1 += m * Rb[bs[k] + lane + 32];
        if (lane == k) mv = m;
    }

    g_battn[p * 64 + lane] = acc0;
    g_battn[p * 64 + lane + 32] = acc1;
    if (lane < 16) Mout[p * 16 + lane] = mv;
}

// ---------------- fusion 1x1 (R4) ---------------------------------------------
#define FUSE_SMEM (65536 + 8448)
__global__ void __launch_bounds__(256) fuse_k(const float* __restrict__ xl,
                                              const float* __restrict__ fb,
                                              float* __restrict__ out) {
    extern __shared__ unsigned char dynsm[];
    u64* wsm = (u64*)dynsm;
    float* vsm = (float*)(dynsm + 65536);

    const int t = threadIdx.x;
    const int b = blockIdx.y;
    const int p0 = blockIdx.x * 256;

    for (int j = t; j < 8192; j += 256) wsm[j] = g_wfu[j];

    const float* ba = g_battn + b * HWP * 64;
    const float* xlb = xl + b * CHW;
    const int cg = t >> 6, q = t & 63;
    u64 acc[16][2];
#pragma unroll
    for (int c = 0; c < 16; c++) {
        acc[c][0] = 0ull;
        acc[c][1] = 0ull;
    }
    __syncthreads();

    for (int cc0 = 0; cc0 < 64; cc0 += 8) {
        __syncthreads();
        for (int i = t; i < 2048; i += 256) {
            int c = i & 7, px = i >> 3;
            vsm[c * 258 + px] = ba[(p0 + px) * 64 + cc0 + c];
        }
        __syncthreads();
#pragma unroll
        for (int cl = 0; cl < 8; cl++) {
            const int cin = cc0 + cl;
            u64 v0 = *(const u64*)&vsm[cl * 258 + 2 * q];
            u64 v1 = *(const u64*)&vsm[cl * 258 + 128 + 2 * q];
            const u64* wb = wsm + cin * 64 + cg * 16;
#pragma unroll
            for (int c = 0; c < 16; c++) {
                u64 w2 = wb[c];
                acc[c][0] = fma2(w2, v0, acc[c][0]);
                acc[c][1] = fma2(w2, v1, acc[c][1]);
            }
        }
    }
#pragma unroll 4
    for (int cin = 64; cin < 128; cin++) {
        u64 v0 = *(const u64*)(xlb + (cin - 64) * HWP + p0 + 2 * q);
        u64 v1 = *(const u64*)(xlb + (cin - 64) * HWP + p0 + 128 + 2 * q);
        const u64* wb = wsm + cin * 64 + cg * 16;
#pragma unroll
        for (int c = 0; c < 16; c++) {
            u64 w2 = wb[c];
            acc[c][0] = fma2(w2, v0, acc[c][0]);
            acc[c][1] = fma2(w2, v1, acc[c][1]);
        }
    }

#pragma unroll
    for (int c = 0; c < 16; c++) {
        const int co = cg * 16 + c;
        const float bb = fb[co];
#pragma unroll
        for (int r = 0; r < 2; r++) {
            float lo, hi;
            upk2(acc[c][r], lo, hi);
            float2 o;
            o.x = lo + bb;
            o.y = hi + bb;
            *(float2*)(out + (b * 64 + co) * HWP + p0 + 128 * r + 2 * q) = o;
        }
    }
}

// ---------------- launch ------------------------------------------------------
extern "C" void kernel_launch(void* const* d_in, const int* in_sizes, int n_in,
                              void* d_out, int out_size) {
    const float* xl = (const float*)d_in[0];
    const float* xr = (const float*)d_in[1];
    const int* xxs = (const int*)d_in[2];
    const int* yys = (const int*)d_in[3];
    const int wbase = (in_sizes[4] == 1) ? 5 : 4;
    const float* rb_w1 = (const float*)d_in[wbase + 0];
    const float* rb_w2 = (const float*)d_in[wbase + 1];
    const float* b1w = (const float*)d_in[wbase + 2];
    const float* b1b = (const float*)d_in[wbase + 3];
    const float* b2w = (const float*)d_in[wbase + 4];
    const float* b2b = (const float*)d_in[wbase + 5];
    const float* b3w = (const float*)d_in[wbase + 6];
    const float* b3b = (const float*)d_in[wbase + 7];
    const float* fw = (const float*)d_in[wbase + 8];
    const float* fb = (const float*)d_in[wbase + 9];

    float* out = (float*)d_out;
    float* Mout = out + BB * CC * HWP;

    cudaFuncSetAttribute(qsr_k, cudaFuncAttributeMaxDynamicSharedMemorySize, QSR_SMEM);
    cudaFuncSetAttribute(fuse_k, cudaFuncAttributeMaxDynamicSharedMemorySize, FUSE_SMEM);

    prep_w<<<224, 256>>>(rb_w1, rb_w2, b1w, b2w, b3w, fw);
    prep_x<<<2048, 256>>>(xl, xr);

    conv_mma<0><<<1024, 256>>>(xl, xr);
    conv_mma<1><<<1024, 256>>>(xl, xr);

    qsr_k<<<dim3(BB * HWP / 256, 3), 256, QSR_SMEM>>>(b1b, b2b, b3b);

    attn_k<<<BB * HWP / 8, 256>>>(xxs, yys, Mout);

    fuse_k<<<dim3(HWP / 256, BB), 256, FUSE_SMEM>>>(xl, fb, out);
}

// round 8
// speedup vs baseline: 1.4786x; 1.0148x over previous
#include <cuda_runtime.h>
#include <cuda_fp16.h>
#include <cstdint>

#define HH 128
#define WW 256
#define HWP 32768
#define CC 64
#define BB 2
#define KK 16
#define CHW (CC * HWP)

typedef unsigned long long u64;
typedef unsigned int u32;

// ---------------- scratch ----------------------------------------------------
__device__ u32 g_xs[4 * HWP * CC];     // packed {hi16,lo16} fp16 split of x, pixel-major
__device__ u32 g_ts[4 * HWP * CC];     // packed split of conv1 output, pixel-major
__device__ float g_buf[4 * CHW];       // conv2 output (fp32, channel-major)
__device__ float g_Q[BB * HWP * CC];
__device__ float g_S[BB * HWP * CC];
__device__ float g_R[BB * HWP * CC];
__device__ float g_battn[BB * HWP * CC];
__device__ u64 g_wf[2 * 9 * 2 * 4 * 8 * 32];  // conv B-frags, pair-ordered (36864)
__device__ u64 g_wq[3][4096];                 // qsr dup-packed
__device__ u64 g_wfu[8192];                   // fuse dup-packed

// ---------------- f32x2 helpers ----------------------------------------------
__device__ __forceinline__ u64 pk2(float lo, float hi) {
    u64 r;
    asm("mov.b64 %0, {%1, %2};" : "=l"(r) : "f"(lo), "f"(hi));
    return r;
}
__device__ __forceinline__ void upk2(u64 v, float& lo, float& hi) {
    asm("mov.b64 {%0, %1}, %2;" : "=f"(lo), "=f"(hi) : "l"(v));
}
__device__ __forceinline__ u64 fma2(u64 a, u64 b, u64 c) {
    u64 d;
    asm("fma.rn.f32x2 %0, %1, %2, %3;" : "=l"(d) : "l"(a), "l"(b), "l"(c));
    return d;
}

// ---------------- fp16 split helpers ------------------------------------------
__device__ __forceinline__ u32 splitpack(float v) {
    __half h = __float2half_rn(v);
    __half l = __float2half_rn(v - __half2float(h));
    return (u32)__half_as_ushort(h) | ((u32)__half_as_ushort(l) << 16);
}

// ---------------- mma / ldmatrix ----------------------------------------------
__device__ __forceinline__ void mma16816(float c[4], const u32 a[4], u32 b0, u32 b1) {
    asm volatile(
        "mma.sync.aligned.m16n8k16.row.col.f32.f16.f16.f32 "
        "{%0,%1,%2,%3},{%4,%5,%6,%7},{%8,%9},{%0,%1,%2,%3};"
        : "+f"(c[0]), "+f"(c[1]), "+f"(c[2]), "+f"(c[3])
        : "r"(a[0]), "r"(a[1]), "r"(a[2]), "r"(a[3]), "r"(b0), "r"(b1));
}
__device__ __forceinline__ void ldsm4(u32 r[4], u32 addr) {
    asm volatile("ldmatrix.sync.aligned.m8n8.x4.shared.b16 {%0,%1,%2,%3}, [%4];"
                 : "=r"(r[0]), "=r"(r[1]), "=r"(r[2]), "=r"(r[3])
                 : "r"(addr));
}
__device__ __forceinline__ u32 smem_u32(const void* p) {
    u32 a;
    asm("{ .reg .u64 t; cvta.to.shared.u64 t, %1; cvt.u32.u64 %0, t; }" : "=r"(a) : "l"(p));
    return a;
}

// ---------------- prep: weights ------------------------------------------------
// conv fragments, pair-ordered: [conv][tap][split][k][np][lane][e]
__global__ void __launch_bounds__(256) prep_w(const float* __restrict__ w1,
                                              const float* __restrict__ w2,
                                              const float* __restrict__ qw,
                                              const float* __restrict__ sw,
                                              const float* __restrict__ rw,
                                              const float* __restrict__ fw) {
    int i = blockIdx.x * 256 + threadIdx.x;  // 0..57343
    if (i < 36864) {
        int conv = i / 18432;
        int r = i % 18432;
        int tap = r / 2048;
        int r2 = r % 2048;
        int split = (r2 >> 10) & 1;
        int k = (r2 >> 8) & 3;
        int low8 = r2 & 255;
        int np = low8 >> 6;
        int lane = (low8 >> 1) & 31;
        int e = low8 & 1;
        int n = np * 2 + e;
        int g = lane >> 2, tig = lane & 3;
        int cin0 = k * 16 + 2 * tig;
        int co = n * 8 + g;
        const float* w = conv ? w2 : w1;
        unsigned short hv[4];
#pragma unroll
        for (int en = 0; en < 4; en++) {
            int cin = cin0 + (en & 1) + (en >> 1) * 8;
            float v = w[(co * 64 + cin) * 9 + tap];
            __half h = __float2half_rn(v);
            __half o = split ? __float2half_rn(v - __half2float(h)) : h;
            hv[en] = __half_as_ushort(o);
        }
        u32 b0 = (u32)hv[0] | ((u32)hv[1] << 16);
        u32 b1 = (u32)hv[2] | ((u32)hv[3] << 16);
        g_wf[i] = (u64)b0 | ((u64)b1 << 32);
    } else if (i < 49152) {
        int j = i - 36864;
        int mat = j >> 12;
        int e = j & 4095;
        int cin = e >> 6, co = e & 63;
        const float* w = (mat == 0) ? qw : (mat == 1) ? sw : rw;
        float v = w[co * 64 + cin];
        g_wq[mat][e] = pk2(v, v);
    } else {
        int j = i - 49152;
        int cin = j >> 6, co = j & 63;
        float v = fw[co * 128 + cin];
        g_wfu[j] = pk2(v, v);
    }
}

// ---------------- prep: split x into pixel-major packed u32 -------------------
__global__ void __launch_bounds__(256) prep_x(const float* __restrict__ xl,
                                              const float* __restrict__ xr) {
    __shared__ float tile[64 * 65];
    const int t = threadIdx.x;
    const int img = blockIdx.x >> 9;
    const int px0 = (blockIdx.x & 511) * 64;
    const float* in = (img < 2) ? (xl + img * CHW) : (xr + (img - 2) * CHW);

    for (int i = t; i < 4096; i += 256) {
        int cin = i >> 6, px = i & 63;
        tile[px * 65 + cin] = in[cin * HWP + px0 + px];
    }
    __syncthreads();
    for (int i = t; i < 4096; i += 256) {
        int px = i >> 6, cin = i & 63;
        g_xs[(img * HWP + px0 + px) * 64 + cin] = splitpack(tile[px * 65 + cin]);
    }
}

// ---------------- conv3x3 via mma.sync + ldmatrix -----------------------------
// CTA = 512 thr (16 warps): two stacked 128-px strips (y0, y0+1) x 64 couts.
// smem: hi plane + lo plane, each 4 rows x 130 px x 72 f16 (144 B/px-row).
#define ROWB 144
#define PLANE (4 * 130 * ROWB)  // 74880
#define CONV_SMEM (2 * PLANE)   // 149760

template <int MODE>
__global__ void __launch_bounds__(512) conv_mma(const float* __restrict__ xl,
                                                const float* __restrict__ xr) {
    extern __shared__ unsigned char sm[];
    const u32 smb = smem_u32(sm);
    const int t = threadIdx.x;
    const int w = t >> 5;
    const int lane = t & 31;
    const int g = lane >> 2, tig = lane & 3;

    const int blk = blockIdx.x;            // 0..511
    const int img = blk >> 7;
    const int rr = blk & 127;
    const int y0 = (rr >> 1) * 2;
    const int x0 = (rr & 1) * 128;

    const u32* inp = ((MODE == 0) ? g_xs : g_ts) + img * HWP * 64;

    // ---- stage 4 rows x 130 px x 64 cin, split into hi/lo planes ----
    for (int i = t; i < 4160; i += 512) {
        int r = i / 1040;
        int rem = i - r * 1040;
        int px = rem >> 3;
        int cing = rem & 7;
        int gy = y0 - 1 + r;
        int gx = x0 - 1 + px;
        uint4 a = make_uint4(0, 0, 0, 0), b = make_uint4(0, 0, 0, 0);
        if ((unsigned)gy < HH && (unsigned)gx < WW) {
            const uint4* src = (const uint4*)(inp + (gy * WW + gx) * 64 + cing * 8);
            a = src[0];
            b = src[1];
        }
        uint4 hv, lv;
        hv.x = __byte_perm(a.x, a.y, 0x5410);
        hv.y = __byte_perm(a.z, a.w, 0x5410);
        hv.z = __byte_perm(b.x, b.y, 0x5410);
        hv.w = __byte_perm(b.z, b.w, 0x5410);
        lv.x = __byte_perm(a.x, a.y, 0x7632);
        lv.y = __byte_perm(a.z, a.w, 0x7632);
        lv.z = __byte_perm(b.x, b.y, 0x7632);
        lv.w = __byte_perm(b.z, b.w, 0x7632);
        int off = (r * 130 + px) * ROWB + cing * 16;
        *(uint4*)(sm + off) = hv;
        *(uint4*)(sm + PLANE + off) = lv;
    }
    __syncthreads();

    const int wy = w >> 3;    // which strip (y0 or y0+1)
    const int wl = w & 7;     // warp position along strip
    // ldmatrix per-lane address component
    const int m = lane >> 3;
    const int rowsel = (lane & 7) + ((m & 1) << 3);
    const int laneoff = rowsel * ROWB + (m >> 1) * 16;

    float acc[8][4];
#pragma unroll
    for (int n = 0; n < 8; n++)
#pragma unroll
        for (int c = 0; c < 4; c++) acc[n][c] = 0.f;

#pragma unroll
    for (int tap = 0; tap < 9; tap++) {
        const int dy = tap / 3, dx = tap - dy * 3;
        const u32 sbase = smb + ((wy + dy) * 130 + dx + wl * 16) * ROWB + laneoff;
        const u64* WT = g_wf + (MODE * 9 + tap) * 2048 + lane * 2;
#pragma unroll
        for (int k = 0; k < 4; k++) {
            u32 ah[4], al[4];
            ldsm4(ah, sbase + k * 32);
            ldsm4(al, sbase + PLANE + k * 32);
            const u64* WH = WT + k * 256;
#pragma unroll
            for (int np = 0; np < 4; np++) {
                uint4 bh = *(const uint4*)(WH + np * 64);
                uint4 bl = *(const uint4*)(WH + 1024 + np * 64);
                mma16816(acc[2 * np], ah, bh.x, bh.y);
                mma16816(acc[2 * np], ah, bl.x, bl.y);
                mma16816(acc[2 * np], al, bh.x, bh.y);
                mma16816(acc[2 * np + 1], ah, bh.z, bh.w);
                mma16816(acc[2 * np + 1], ah, bl.z, bl.w);
                mma16816(acc[2 * np + 1], al, bh.z, bh.w);
            }
        }
    }

    const int y = y0 + wy;
    const int bp = y * WW + x0 + wl * 16 + g;  // pixel row g; +8 for row g+8
    if (MODE == 0) {
        u32* o0 = g_ts + (img * HWP + bp) * 64;
        u32* o1 = o0 + 8 * 64;
#pragma unroll
        for (int n = 0; n < 8; n++) {
            const int co0 = n * 8 + 2 * tig;
            float v0 = acc[n][0], v1 = acc[n][1], v2 = acc[n][2], v3 = acc[n][3];
            v0 = v0 > 0.f ? v0 : 0.1f * v0;
            v1 = v1 > 0.f ? v1 : 0.1f * v1;
            v2 = v2 > 0.f ? v2 : 0.1f * v2;
            v3 = v3 > 0.f ? v3 : 0.1f * v3;
            u32 p0 = splitpack(v0), p1 = splitpack(v1);
            u32 p2 = splitpack(v2), p3 = splitpack(v3);
            *(u64*)(o0 + co0) = (u64)p0 | ((u64)p1 << 32);
            *(u64*)(o1 + co0) = (u64)p2 | ((u64)p3 << 32);
        }
    } else {
        const float* res = (img < 2) ? (xl + img * CHW) : (xr + (img - 2) * CHW);
        float* ob = g_buf + img * CHW;
#pragma unroll
        for (int n = 0; n < 8; n++) {
            const int co0 = n * 8 + 2 * tig;
            ob[co0 * HWP + bp] = acc[n][0] + res[co0 * HWP + bp];
            ob[(co0 + 1) * HWP + bp] = acc[n][1] + res[(co0 + 1) * HWP + bp];
            ob[co0 * HWP + bp + 8] = acc[n][2] + res[co0 * HWP + bp + 8];
            ob[(co0 + 1) * HWP + bp + 8] = acc[n][3] + res[(co0 + 1) * HWP + bp + 8];
        }
    }
}

// ---------------- Q/S/R 1x1: smem-staged GEMM ---------------------------------
#define QSR_SMEM (32768 + 17408)
__global__ void __launch_bounds__(256, 2) qsr_k(const float* __restrict__ b1b,
                                                const float* __restrict__ b2b,
                                                const float* __restrict__ b3b) {
    extern __shared__ unsigned char dynsm[];
    u64* wsm = (u64*)dynsm;
    float* tile = (float*)(dynsm + 32768);
    float* st = (float*)(dynsm + 32768);

    const int t = threadIdx.x;
    const int mat = blockIdx.y;
    const int p0 = blockIdx.x * 256;
    const int b = p0 >> 15;
    const int lp = p0 & 32767;

    const float* in = g_buf + (((mat == 0) ? 0 : 2) + b) * CHW + lp;
    float* outp = ((mat == 0) ? g_Q : (mat == 1) ? g_S : g_R) + p0 * 64;
    const float* bias = (mat == 0) ? b1b : (mat == 1) ? b2b : b3b;

    {
        const u64* ws = g_wq[mat];
        for (int j = t; j < 4096; j += 256) wsm[j] = ws[j];
    }

    const int cg = t >> 5;
    const int tx = t & 31;

    u64 acc[8][4];
#pragma unroll
    for (int co = 0; co < 8; co++)
#pragma unroll
        for (int j = 0; j < 4; j++) acc[co][j] = 0ull;

    for (int cc0 = 0; cc0 < 64; cc0 += 16) {
        __syncthreads();
#pragma unroll
        for (int k = 0; k < 16; k++) {
            int j = t + k * 256;
            int cin = j >> 8, px = j & 255;
            tile[j] = in[(cc0 + cin) * HWP + px];
        }
        __syncthreads();
#pragma unroll 4
        for (int ci = 0; ci < 16; ci++) {
            u64 v[4];
#pragma unroll
            for (int j = 0; j < 4; j++) v[j] = *(const u64*)&tile[ci * 256 + 2 * tx + 64 * j];
            const u64* wb = wsm + (cc0 + ci) * 64 + cg * 8;
#pragma unroll
            for (int co = 0; co < 8; co++) {
                u64 w2 = wb[co];
#pragma unroll
                for (int j = 0; j < 4; j++) acc[co][j] = fma2(w2, v[j], acc[co][j]);
            }
        }
    }

#pragma unroll
    for (int j = 0; j < 4; j++) {
        __syncthreads();
#pragma unroll
        for (int co = 0; co < 8; co++) {
            float lo, hi;
            upk2(acc[co][j], lo, hi);
            st[(2 * tx) * 65 + cg * 8 + co] = lo;
            st[(2 * tx + 1) * 65 + cg * 8 + co] = hi;
        }
        __syncthreads();
        for (int i = t; i < 4096; i += 256) {
            int px = i >> 6, c = i & 63;
            outp[(64 * j + px) * 64 + c] = st[px * 65 + c] + bias[c];
        }
    }
}

// ---------------- attention: warp per pixel ----------------------------------
__global__ void __launch_bounds__(256) attn_k(const int* __restrict__ xxs,
                                              const int* __restrict__ yys,
                                              float* __restrict__ Mout) {
    const int t = threadIdx.x;
    const int lane = t & 31;
    const int p = blockIdx.x * 8 + (t >> 5);
    const int b = p >> 15;

    int fl = 0;
    if (lane < 16) fl = xxs[p * 16 + lane] * WW + yys[p * 16 + lane];

    const float q0 = g_Q[p * 64 + lane];
    const float q1 = g_Q[p * 64 + lane + 32];
    const float* Sb = g_S + b * HWP * 64;
    const float* Rb = g_R + b * HWP * 64;

    float sc[16];
    int bs[16];
#pragma unroll
    for (int k = 0; k < 16; k++) {
        int fk = __shfl_sync(0xffffffffu, fl, k);
        int base = fk * 64;
        bs[k] = base;
        float part = q0 * Sb[base + lane] + q1 * Sb[base + lane + 32];
#pragma unroll
        for (int o = 16; o; o >>= 1) part += __shfl_xor_sync(0xffffffffu, part, o);
        sc[k] = part;
    }

    float mx = sc[0];
#pragma unroll
    for (int k = 1; k < 16; k++) mx = fmaxf(mx, sc[k]);
    float sum = 0.f;
#pragma unroll
    for (int k = 0; k < 16; k++) {
        sc[k] = __expf(sc[k] - mx);
        sum += sc[k];
    }
    const float inv = 1.f / sum;

    float acc0 = 0.f, acc1 = 0.f, mv = 0.f;
#pragma unroll
    for (int k = 0; k < 16; k++) {
        float m = sc[k] * inv;
        acc0 += m * Rb[bs[k] + lane];
        acc1 += m * Rb[bs[k] + lane + 32];
        if (lane == k) mv = m;
    }

    g_battn[p * 64 + lane] = acc0;
    g_battn[p * 64 + lane + 32] = acc1;
    if (lane < 16) Mout[p * 16 + lane] = mv;
}

// ---------------- fusion 1x1 ---------------------------------------------------
#define FUSE_SMEM (65536 + 8448)
__global__ void __launch_bounds__(256) fuse_k(const float* __restrict__ xl,
                                              const float* __restrict__ fb,
                                              float* __restrict__ out) {
    extern __shared__ unsigned char dynsm[];
    u64* wsm = (u64*)dynsm;
    float* vsm = (float*)(dynsm + 65536);

    const int t = threadIdx.x;
    const int b = blockIdx.y;
    const int p0 = blockIdx.x * 256;

    for (int j = t; j < 8192; j += 256) wsm[j] = g_wfu[j];

    const float* ba = g_battn + b * HWP * 64;
    const float* xlb = xl + b * CHW;
    const int cg = t >> 6, q = t & 63;
    u64 acc[16][2];
#pragma unroll
    for (int c = 0; c < 16; c++) {
        acc[c][0] = 0ull;
        acc[c][1] = 0ull;
    }
    __syncthreads();

    for (int cc0 = 0; cc0 < 64; cc0 += 8) {
        __syncthreads();
        for (int i = t; i < 2048; i += 256) {
            int c = i & 7, px = i >> 3;
            vsm[c * 258 + px] = ba[(p0 + px) * 64 + cc0 + c];
        }
        __syncthreads();
#pragma unroll
        for (int cl = 0; cl < 8; cl++) {
            const int cin = cc0 + cl;
            u64 v0 = *(const u64*)&vsm[cl * 258 + 2 * q];
            u64 v1 = *(const u64*)&vsm[cl * 258 + 128 + 2 * q];
            const u64* wb = wsm + cin * 64 + cg * 16;
#pragma unroll
            for (int c = 0; c < 16; c++) {
                u64 w2 = wb[c];
                acc[c][0] = fma2(w2, v0, acc[c][0]);
                acc[c][1] = fma2(w2, v1, acc[c][1]);
            }
        }
    }
#pragma unroll 4
    for (int cin = 64; cin < 128; cin++) {
        u64 v0 = *(const u64*)(xlb + (cin - 64) * HWP + p0 + 2 * q);
        u64 v1 = *(const u64*)(xlb + (cin - 64) * HWP + p0 + 128 + 2 * q);
        const u64* wb = wsm + cin * 64 + cg * 16;
#pragma unroll
        for (int c = 0; c < 16; c++) {
            u64 w2 = wb[c];
            acc[c][0] = fma2(w2, v0, acc[c][0]);
            acc[c][1] = fma2(w2, v1, acc[c][1]);
        }
    }

#pragma unroll
    for (int c = 0; c < 16; c++) {
        const int co = cg * 16 + c;
        const float bb = fb[co];
#pragma unroll
        for (int r = 0; r < 2; r++) {
            float lo, hi;
            upk2(acc[c][r], lo, hi);
            float2 o;
            o.x = lo + bb;
            o.y = hi + bb;
            *(float2*)(out + (b * 64 + co) * HWP + p0 + 128 * r + 2 * q) = o;
        }
    }
}

// ---------------- launch ------------------------------------------------------
extern "C" void kernel_launch(void* const* d_in, const int* in_sizes, int n_in,
                              void* d_out, int out_size) {
    const float* xl = (const float*)d_in[0];
    const float* xr = (const float*)d_in[1];
    const int* xxs = (const int*)d_in[2];
    const int* yys = (const int*)d_in[3];
    const int wbase = (in_sizes[4] == 1) ? 5 : 4;
    const float* rb_w1 = (const float*)d_in[wbase + 0];
    const float* rb_w2 = (const float*)d_in[wbase + 1];
    const float* b1w = (const float*)d_in[wbase + 2];
    const float* b1b = (const float*)d_in[wbase + 3];
    const float* b2w = (const float*)d_in[wbase + 4];
    const float* b2b = (const float*)d_in[wbase + 5];
    const float* b3w = (const float*)d_in[wbase + 6];
    const float* b3b = (const float*)d_in[wbase + 7];
    const float* fw = (const float*)d_in[wbase + 8];
    const float* fb = (const float*)d_in[wbase + 9];

    float* out = (float*)d_out;
    float* Mout = out + BB * CC * HWP;

    cudaFuncSetAttribute(conv_mma<0>, cudaFuncAttributeMaxDynamicSharedMemorySize, CONV_SMEM);
    cudaFuncSetAttribute(conv_mma<1>, cudaFuncAttributeMaxDynamicSharedMemorySize, CONV_SMEM);
    cudaFuncSetAttribute(qsr_k, cudaFuncAttributeMaxDynamicSharedMemorySize, QSR_SMEM);
    cudaFuncSetAttribute(fuse_k, cudaFuncAttributeMaxDynamicSharedMemorySize, FUSE_SMEM);

    prep_w<<<224, 256>>>(rb_w1, rb_w2, b1w, b2w, b3w, fw);
    prep_x<<<2048, 256>>>(xl, xr);

    conv_mma<0><<<512, 512, CONV_SMEM>>>(xl, xr);
    conv_mma<1><<<512, 512, CONV_SMEM>>>(xl, xr);

    qsr_k<<<dim3(BB * HWP / 256, 3), 256, QSR_SMEM>>>(b1b, b2b, b3b);

    attn_k<<<BB * HWP / 8, 256>>>(xxs, yys, Mout);

    fuse_k<<<dim3(HWP / 256, BB), 256, FUSE_SMEM>>>(xl, fb, out);
}